// round 5
// baseline (speedup 1.0000x reference)
#include <cuda_runtime.h>
#include <stdint.h>

#define N_PTS   50000
#define B_ROWS  512
#define E_DIM   16
#define KSEL    20
#define KP1     21            // top-21: lane 0 is always "self", dropped at the end
#define TILE    128           // candidates per tile (1 per sub-group thread)
#define BTHR    256
#define G_ROWS  8
#define SPLITS  2
#define NGRP    (B_ROWS / G_ROWS)      // 64
#define NBLK    (NGRP * 2 * SPLITS)    // 256
#define HID     64
#define FULLM   0xffffffffu

typedef unsigned long long ull;

__device__ float g_nrm[2][N_PTS];
__device__ float g_feats[B_ROWS][8];
__device__ float g_pval[2][NGRP][SPLITS][G_ROWS][KP1];
__device__ int   g_pidx[2][NGRP][SPLITS][G_ROWS][KP1];
__device__ int   g_flag[2][NGRP];
__device__ int   g_nbar = 0;
__device__ int   g_done = 0;

static __device__ __forceinline__ float finf() { return __int_as_float(0x7f800000); }

static __device__ __forceinline__ ull pk2(float lo, float hi) {
    ull r; asm("mov.b64 %0,{%1,%2};" : "=l"(r) : "f"(lo), "f"(hi)); return r;
}
static __device__ __forceinline__ void upk2(ull v, float& lo, float& hi) {
    asm("mov.b64 {%0,%1},%2;" : "=f"(lo), "=f"(hi) : "l"(v));
}
static __device__ __forceinline__ ull fma2(ull a, ull b, ull c) {
    ull d; asm("fma.rn.f32x2 %0,%1,%2,%3;" : "=l"(d) : "l"(a), "l"(b), "l"(c)); return d;
}

__global__ __launch_bounds__(BTHR, 2)
void knn_kernel(const float* __restrict__ emb0, const float* __restrict__ emb1,
                const float* __restrict__ rctx0, const float* __restrict__ rctx1,
                const int* __restrict__ idx0, const int* __restrict__ idx1,
                const float* __restrict__ mean_in, const float* __restrict__ std_in,
                const float* __restrict__ W1, const float* __restrict__ b1,
                const float* __restrict__ Wm, const float* __restrict__ bm,
                const float* __restrict__ Ws, const float* __restrict__ bs,
                float* __restrict__ out, int n) {
    const int grp   = blockIdx.x;
    const int set   = blockIdx.y;
    const int split = blockIdx.z;
    const float* __restrict__ emb  = set ? emb1 : emb0;
    const float* __restrict__ rctx = set ? rctx1 : rctx0;
    const int*   __restrict__ idxp = set ? idx1 : idx0;

    const int rowbase = grp * G_ROWS;
    const int tid  = threadIdx.x;
    const int lane = tid & 31;
    const int w    = tid >> 5;            // warp id: owns row w in drain phase
    const int sg   = tid >> 7;            // sub-group 0/1 -> rows 4sg..4sg+3
    const int tid7 = tid & 127;

    __shared__ float qv_sm[2][G_ROWS][TILE];
    __shared__ int   qi_sm[2][G_ROWS][TILE];
    __shared__ int   qcnt[2][G_ROWS];
    __shared__ float thresh_sm[G_ROWS];
    __shared__ int   smflag[2];

    // ---------------- norm pre-pass (grid-wide, all blocks resident) -------
    {
        const int bid = grp + NGRP * (set + 2 * split);
        for (int i = bid * BTHR + tid; i < 2 * N_PTS; i += NBLK * BTHR) {
            int s2 = i / N_PTS, j = i - s2 * N_PTS;
            const float4* p = reinterpret_cast<const float4*>(
                (s2 ? emb1 : emb0) + (size_t)j * E_DIM);
            float4 a = p[0], b = p[1], c = p[2], d = p[3];
            float nm = a.x*a.x + a.y*a.y + a.z*a.z + a.w*a.w
                     + b.x*b.x + b.y*b.y + b.z*b.z + b.w*b.w
                     + c.x*c.x + c.y*c.y + c.z*c.z + c.w*c.w
                     + d.x*d.x + d.y*d.y + d.z*d.z + d.w*d.w;
            g_nrm[s2][j] = nm;
        }
    }
    // smem init (before the global barrier's __syncthreads)
    if (tid < 16) qcnt[tid >> 3][tid & 7] = 0;
    if (tid < 8)  thresh_sm[tid] = finf();
    __threadfence();
    __syncthreads();
    if (tid == 0) {
        atomicAdd(&g_nbar, 1);
        while (*(volatile int*)&g_nbar < NBLK) __nanosleep(64);
    }
    __syncthreads();
    __threadfence();

    // ---------------- stage queries into registers -------------------------
    ull q2[4][8];
#pragma unroll
    for (int rr = 0; rr < 4; rr++) {
        int si = idxp[rowbase + 4 * sg + rr];
        const float4* qp = reinterpret_cast<const float4*>(emb + (size_t)si * E_DIM);
#pragma unroll
        for (int c = 0; c < 4; c++) {
            float4 v = qp[c];
            q2[rr][2 * c + 0] = pk2(-2.f * v.x, -2.f * v.y);
            q2[rr][2 * c + 1] = pk2(-2.f * v.z, -2.f * v.w);
        }
    }

    const int halfn = (n + SPLITS - 1) / SPLITS;
    const int jbeg  = split * halfn;
    const int jend  = min(n, jbeg + halfn);
    const int ntiles = (jend - jbeg + TILE - 1) / TILE;

    // ---------------- top-21 state (lanes 0..20 ascending) -----------------
    float kval   = finf();
    int   kidx   = -1;
    float thresh = finf();

    auto insert = [&](float bv, int bj) {
        float pv = __shfl_up_sync(FULLM, kval, 1);
        int   pj = __shfl_up_sync(FULLM, kidx, 1);
        if (lane < KP1 && bv < kval) {
            if (lane == 0 || bv >= pv) { kval = bv; kidx = bj; }
            else                        { kval = pv; kidx = pj; }
        }
        thresh = __shfl_sync(FULLM, kval, KP1 - 1);
    };

    // ---------------- main loop --------------------------------------------
    for (int t = 0; t < ntiles; t++) {
        const int buf = t & 1;
        const int j   = jbeg + t * TILE + tid7;
        const bool vld = (j < jend);

        ull e[8]; float nm = 0.f;
        if (vld) {
            const ulonglong2* p = reinterpret_cast<const ulonglong2*>(emb + (size_t)j * E_DIM);
            ulonglong2 a = p[0], b = p[1], c = p[2], d = p[3];
            e[0]=a.x; e[1]=a.y; e[2]=b.x; e[3]=b.y; e[4]=c.x; e[5]=c.y; e[6]=d.x; e[7]=d.y;
            nm = g_nrm[set][j];
        }

        ull acc[4];
#pragma unroll
        for (int rr = 0; rr < 4; rr++) acc[rr] = pk2(nm, 0.f);
#pragma unroll
        for (int c = 0; c < 8; c++) {
            ull ec = e[c];
            acc[0] = fma2(q2[0][c], ec, acc[0]);
            acc[1] = fma2(q2[1][c], ec, acc[1]);
            acc[2] = fma2(q2[2][c], ec, acc[2]);
            acc[3] = fma2(q2[3][c], ec, acc[3]);
        }

        if (vld) {
#pragma unroll
            for (int rr = 0; rr < 4; rr++) {
                float lo, hi; upk2(acc[rr], lo, hi);
                float s  = lo + hi;                 // |e|^2 - 2 a.e
                int   r  = 4 * sg + rr;
                float th = thresh_sm[r];            // stale-safe (monotone dec.)
                if (s < th) {
                    int p = atomicAdd(&qcnt[buf][r], 1);
                    qv_sm[buf][r][p] = s;
                    qi_sm[buf][r][p] = j;
                }
            }
        }
        __syncthreads();

        // ---- warp w drains row w's queue ----
        int m = qcnt[buf][w];
        for (int b0 = 0; b0 < m; b0 += 32) {
            int  k   = b0 + lane;
            bool act = (k < m);
            float bvl = act ? qv_sm[buf][w][k] : finf();
            int   bjl = act ? qi_sm[buf][w][k] : 0;
            unsigned msk = __ballot_sync(FULLM, act && bvl < thresh);
            while (msk) {
                int src = __ffs(msk) - 1; msk &= msk - 1;
                float bv = __shfl_sync(FULLM, bvl, src);
                int   bj = __shfl_sync(FULLM, bjl, src);
                if (bv < thresh) insert(bv, bj);
            }
        }
        if (lane == 0) {
            qcnt[buf][w]  = 0;
            thresh_sm[w]  = thresh;
        }
    }

    // ---------------- split rendezvous -------------------------------------
    if (lane < KP1) {
        g_pval[set][grp][split][w][lane] = kval;
        g_pidx[set][grp][split][w][lane] = kidx;
    }
    __threadfence();
    __syncthreads();
    if (tid == 0) smflag[0] = atomicAdd(&g_flag[set][grp], 1);
    __syncthreads();

    if (smflag[0] == 1) {                 // second arrival merges + features
        __threadfence();
        const int po = 1 - split;
        for (int i = 0; i < KP1; i++) {
            float bv = g_pval[set][grp][po][w][i];
            int   bj = g_pidx[set][grp][po][w][i];
            if (bv < thresh) insert(bv, bj);
        }
        // lane 0 now holds "self" (s = -|a|^2, the strict minimum): drop it.
        const int row = rowbase + w;
        float na = g_nrm[set][idxp[row]];
        float wgt = 0.f, sel = 0.f;
        if (lane >= 1 && lane < KP1) {
            float d2  = fmaxf(kval + na, 0.f);
            float sim = sqrtf(d2) + 0.001f;
            wgt = __expf(-sim);
            sel = rctx[(size_t)row * n + kidx];
        }
        float sw = wgt, ssw = sel * wgt, ss = sel, ss2 = sel * sel;
#pragma unroll
        for (int off = 16; off; off >>= 1) {
            sw  += __shfl_xor_sync(FULLM, sw,  off);
            ssw += __shfl_xor_sync(FULLM, ssw, off);
            ss  += __shfl_xor_sync(FULLM, ss,  off);
            ss2 += __shfl_xor_sync(FULLM, ss2, off);
        }
        if (lane == 0) {
            g_feats[row][0 + set] = sw;
            g_feats[row][2 + set] = ssw / sw;
            float var = (ss2 - ss * ss / (float)KSEL) / (float)(KSEL - 1);
            g_feats[row][4 + set] = sqrtf(fmaxf(var, 0.f));
        }
        if (tid == 0) g_flag[set][grp] = 0;
    }

    // ---------------- global tail: MLP -------------------------------------
    __threadfence();
    __syncthreads();
    if (tid == 0) smflag[1] = atomicAdd(&g_done, 1);
    __syncthreads();
    if (smflag[1] != NBLK - 1) return;
    __threadfence();

#pragma unroll
    for (int rr = 0; rr < 2; rr++) {
        int r = tid + BTHR * rr;
        float f[8];
#pragma unroll
        for (int i = 0; i < 6; i++) f[i] = g_feats[r][i];
        f[6] = mean_in[r];
        f[7] = std_in[r];
        float m = bm[0], sd = bs[0];
#pragma unroll 4
        for (int jj = 0; jj < HID; jj++) {
            float h = b1[jj];
#pragma unroll
            for (int i = 0; i < 8; i++) h = fmaf(f[i], W1[i * HID + jj], h);
            h = fmaxf(h, 0.f);
            m  = fmaf(h, Wm[jj], m);
            sd = fmaf(h, Ws[jj], sd);
        }
        out[r]          = m;
        out[B_ROWS + r] = sd;
    }
    if (tid == 0) { g_done = 0; g_nbar = 0; }
}

// ---------------------------------------------------------------------------
extern "C" void kernel_launch(void* const* d_in, const int* in_sizes, int n_in,
                              void* d_out, int out_size) {
    const float* emb0    = (const float*)d_in[0];
    const float* emb1    = (const float*)d_in[1];
    const float* rctx0   = (const float*)d_in[2];
    const float* rctx1   = (const float*)d_in[3];
    const int*   idx0    = (const int*)  d_in[4];
    const int*   idx1    = (const int*)  d_in[5];
    const float* mean_in = (const float*)d_in[6];
    const float* std_in  = (const float*)d_in[7];
    const float* W1      = (const float*)d_in[8];
    const float* b1      = (const float*)d_in[9];
    const float* Wm      = (const float*)d_in[10];
    const float* bm      = (const float*)d_in[11];
    const float* Ws      = (const float*)d_in[12];
    const float* bs      = (const float*)d_in[13];

    int n = in_sizes[0] / E_DIM;    // 50000

    dim3 grid(NGRP, 2, SPLITS);
    knn_kernel<<<grid, BTHR>>>(emb0, emb1, rctx0, rctx1, idx0, idx1,
                               mean_in, std_in, W1, b1, Wm, bm, Ws, bs,
                               (float*)d_out, n);
}